// round 15
// baseline (speedup 1.0000x reference)
#include <cuda_runtime.h>
#include <cuda_bf16.h>
#include <math.h>

// ---------------- Problem constants ----------------
#define B_ROWS   1024
#define OBS_DIM  512
#define ACT_DIM  64
#define KD       128
#define CAP      131072

// ---------------- Phase B config ----------------
#define MBLOCKS  8                      // 128 rows each
#define KTILE    128                    // keys per tile
#define NKT      (CAP / KTILE)          // 1024 tiles
#define NSPLIT   18                     // 8*18 = 144 CTAs = 1 wave
#define NCTAS    (MBLOCKS * NSPLIT)     // 144
#define NPART    (NSPLIT * 2)           // 36 partials per row
#define PSTRIDE  40

// smem offsets (bytes, from dynamic smem base)
#define OFF_AHI  0                      // 32KB (128x128 bf16)
#define OFF_ALO  32768
#define OFF_B    65536                  // + stage*65536; hi 32KB, lo at +32768
#define OFF_VAL  196608                 // 4 slots * 512B
#define SMEM_REQ 198656

// ---------------- Device scratch (no cudaMalloc allowed) ----------------
__device__ uint4 g_khi[NKT * 2048];         // 32 MB swizzled bf16-hi key images (128-row tiles)
__device__ uint4 g_klo[NKT * 2048];         // 32 MB swizzled bf16-lo key images
__device__ uint4 g_ahi[MBLOCKS * 2048];     // swizzled bf16-hi h images (128-row tiles)
__device__ uint4 g_alo[MBLOCKS * 2048];
__device__ float g_m0 [B_ROWS];             // per-row fixed softmax shift (log2 units)
__device__ float g_pl [B_ROWS * PSTRIDE];
__device__ float g_pa [B_ROWS * PSTRIDE];
__device__ unsigned g_done;                 // phaseB completion counter (reset by phaseA)

// ---------------- Helpers ----------------
__device__ __forceinline__ float ex2(float x) {
    float r; asm("ex2.approx.ftz.f32 %0, %1;" : "=f"(r) : "f"(x)); return r;
}
__device__ __forceinline__ unsigned smem_u32(const void* p) {
    return (unsigned)__cvta_generic_to_shared((void*)p);
}
__device__ __forceinline__ void cp_async16(unsigned dst, const void* src) {
    asm volatile("cp.async.cg.shared.global [%0], [%1], 16;" :: "r"(dst), "l"(src) : "memory");
}
__device__ __forceinline__ void cp_commit() {
    asm volatile("cp.async.commit_group;" ::: "memory");
}
// named barrier: 128 threads of one wn-group
__device__ __forceinline__ void barg(int g) {
    asm volatile("bar.sync %0, 128;" :: "r"(g + 1) : "memory");
}

__device__ __forceinline__ void ldsm4(unsigned* r, unsigned addr) {
    asm volatile("ldmatrix.sync.aligned.m8n8.x4.shared.b16 {%0,%1,%2,%3}, [%4];"
                 : "=r"(r[0]), "=r"(r[1]), "=r"(r[2]), "=r"(r[3]) : "r"(addr));
}
__device__ __forceinline__ void mma_bf16(float* c, const unsigned* a, const unsigned* b) {
    asm volatile("mma.sync.aligned.m16n8k16.row.col.f32.bf16.bf16.f32 "
                 "{%0,%1,%2,%3}, {%4,%5,%6,%7}, {%8,%9}, {%0,%1,%2,%3};"
                 : "+f"(c[0]), "+f"(c[1]), "+f"(c[2]), "+f"(c[3])
                 : "r"(a[0]), "r"(a[1]), "r"(a[2]), "r"(a[3]), "r"(b[0]), "r"(b[1]));
}

// Swizzled tile-image uint4 index: row r, chunk cc = k>>3; chunk stored at cc ^ (r&7).
__device__ __forceinline__ unsigned img_idx(int r, int k) {
    unsigned cc = (unsigned)(k >> 3);
    return ((unsigned)r << 4) + (cc ^ ((unsigned)r & 7u));
}
__device__ __forceinline__ unsigned sw_off(unsigned r, unsigned cc) {
    return (r << 8) + ((cc ^ (r & 7u)) << 4);
}

__device__ __forceinline__ void split8(const float* x, uint4& hi, uint4& lo) {
    unsigned h[4], l[4];
    #pragma unroll
    for (int p = 0; p < 4; p++) {
        float a = x[2 * p], b = x[2 * p + 1];
        __nv_bfloat162 hh = __floats2bfloat162_rn(a, b);
        float ar = a - __bfloat162float(__low2bfloat16(hh));
        float br = b - __bfloat162float(__high2bfloat16(hh));
        __nv_bfloat162 ll = __floats2bfloat162_rn(ar, br);
        h[p] = *reinterpret_cast<unsigned*>(&hh);
        l[p] = *reinterpret_cast<unsigned*>(&ll);
    }
    hi = make_uint4(h[0], h[1], h[2], h[3]);
    lo = make_uint4(l[0], l[1], l[2], l[3]);
}

// Stage one 128x32 fp32 weight chunk into s_w (pad-33 rows), coalesced.
__device__ __forceinline__ void stage_w(float* s_w, const float* __restrict__ W,
                                        int KIN, int k0, int tid)
{
    #pragma unroll
    for (int u = 0; u < 4; u++) {
        int idx = u * 256 + tid;
        int jjr = idx >> 3;
        int c4  = idx & 7;
        float4 w = __ldg((const float4*)(W + jjr * KIN + k0) + c4);
        float* d = s_w + jjr * 33 + c4 * 4;
        d[0] = w.x; d[1] = w.y; d[2] = w.z; d[3] = w.w;
    }
}

// =====================================================================
// Phase A: fused MLP with smem-staged weights. 8 rows/block, grid 128.
// Writes swizzled bf16 hi/lo H images (128-row tiles) + per-row M0.
// Block 0 also resets the phaseB completion counter.
// =====================================================================
__global__ void __launch_bounds__(256)
phaseA_kernel(const float* __restrict__ obs,   const float* __restrict__ action,
              const float* __restrict__ pW,    const float* __restrict__ pb,
              const float* __restrict__ t1W,   const float* __restrict__ t1b,
              const float* __restrict__ t2W,   const float* __restrict__ t2b,
              const float* __restrict__ ltemp)
{
    __shared__ float s_obs[8 * 516];
    __shared__ float s_in [8 * 196];
    __shared__ float s_h1 [8 * 132];
    __shared__ float s_w  [128 * 33];
    __shared__ float s_rn [8];

    const int tid = threadIdx.x;
    const int rb  = blockIdx.x * 8;

    if (blockIdx.x == 0 && tid == 0) g_done = 0;   // reset phaseB counter

    #pragma unroll
    for (int j = 0; j < 4; j++) {
        int g  = j * 256 + tid;
        int r  = g >> 7, k4 = g & 127;
        float4 v = ((const float4*)obs)[(rb + r) * 128 + k4];
        *(float4*)&s_obs[r * 516 + k4 * 4] = v;
    }
    #pragma unroll
    for (int j = 0; j < 2; j++) {
        int g = j * 256 + tid;
        int r = g >> 6, a = g & 63;
        s_in[r * 196 + 128 + a] = action[(rb + r) * 64 + a];
    }

    const int jj = tid & 127;
    const int rg = tid >> 7;

    // ---- predictor: 512 -> 128 ----
    float acc[4] = {0.f, 0.f, 0.f, 0.f};
    for (int c = 0; c < 16; c++) {
        __syncthreads();
        stage_w(s_w, pW, 512, c * 32, tid);
        __syncthreads();
        #pragma unroll
        for (int kk = 0; kk < 32; kk += 4) {
            float w0 = s_w[jj * 33 + kk], w1 = s_w[jj * 33 + kk + 1];
            float w2 = s_w[jj * 33 + kk + 2], w3 = s_w[jj * 33 + kk + 3];
            #pragma unroll
            for (int i = 0; i < 4; i++) {
                float4 o = *(const float4*)&s_obs[(rg * 4 + i) * 516 + c * 32 + kk];
                acc[i] = fmaf(w0, o.x, acc[i]);
                acc[i] = fmaf(w1, o.y, acc[i]);
                acc[i] = fmaf(w2, o.z, acc[i]);
                acc[i] = fmaf(w3, o.w, acc[i]);
            }
        }
    }
    float bias0 = pb[jj];
    float raw[4];
    #pragma unroll
    for (int i = 0; i < 4; i++) {
        raw[i] = acc[i] + bias0;
        s_in[(rg * 4 + i) * 196 + jj] = raw[i];
    }
    __syncthreads();

    // ---- L2 norms ----
    {
        int w = tid >> 5, lane = tid & 31;
        float ss = 0.f;
        #pragma unroll
        for (int c = lane; c < 128; c += 32) {
            float x = s_in[w * 196 + c];
            ss = fmaf(x, x, ss);
        }
        #pragma unroll
        for (int d = 16; d > 0; d >>= 1) ss += __shfl_xor_sync(0xffffffffu, ss, d);
        if (lane == 0) s_rn[w] = 1.0f / fmaxf(sqrtf(ss), 1e-12f);
    }
    __syncthreads();
    #pragma unroll
    for (int i = 0; i < 4; i++)
        s_in[(rg * 4 + i) * 196 + jj] = raw[i] * s_rn[rg * 4 + i];

    // ---- layer 1: 192 -> 128, relu ----
    float acc1[4] = {0.f, 0.f, 0.f, 0.f};
    for (int c = 0; c < 6; c++) {
        __syncthreads();
        stage_w(s_w, t1W, 192, c * 32, tid);
        __syncthreads();
        #pragma unroll
        for (int kk = 0; kk < 32; kk += 4) {
            float w0 = s_w[jj * 33 + kk], w1 = s_w[jj * 33 + kk + 1];
            float w2 = s_w[jj * 33 + kk + 2], w3 = s_w[jj * 33 + kk + 3];
            #pragma unroll
            for (int i = 0; i < 4; i++) {
                float4 o = *(const float4*)&s_in[(rg * 4 + i) * 196 + c * 32 + kk];
                acc1[i] = fmaf(w0, o.x, acc1[i]);
                acc1[i] = fmaf(w1, o.y, acc1[i]);
                acc1[i] = fmaf(w2, o.z, acc1[i]);
                acc1[i] = fmaf(w3, o.w, acc1[i]);
            }
        }
    }
    float bias1 = t1b[jj];
    __syncthreads();
    #pragma unroll
    for (int i = 0; i < 4; i++)
        s_h1[(rg * 4 + i) * 132 + jj] = fmaxf(acc1[i] + bias1, 0.0f);

    // ---- layer 2: 128 -> 128 ----
    float acc2[4] = {0.f, 0.f, 0.f, 0.f};
    for (int c = 0; c < 4; c++) {
        __syncthreads();
        stage_w(s_w, t2W, 128, c * 32, tid);
        __syncthreads();
        #pragma unroll
        for (int kk = 0; kk < 32; kk += 4) {
            float w0 = s_w[jj * 33 + kk], w1 = s_w[jj * 33 + kk + 1];
            float w2 = s_w[jj * 33 + kk + 2], w3 = s_w[jj * 33 + kk + 3];
            #pragma unroll
            for (int i = 0; i < 4; i++) {
                float4 o = *(const float4*)&s_h1[(rg * 4 + i) * 132 + c * 32 + kk];
                acc2[i] = fmaf(w0, o.x, acc2[i]);
                acc2[i] = fmaf(w1, o.y, acc2[i]);
                acc2[i] = fmaf(w2, o.z, acc2[i]);
                acc2[i] = fmaf(w3, o.w, acc2[i]);
            }
        }
    }
    float bias2 = t2b[jj];
    __syncthreads();
    #pragma unroll
    for (int i = 0; i < 4; i++)
        s_h1[(rg * 4 + i) * 132 + jj] = acc2[i] + bias2;   // H rows
    __syncthreads();

    // ---- per-row softmax shift M0 = 0.5*|H|*(1/T)*log2e ----
    {
        const float L2E = 1.4426950408889634f;
        float invT = ex2(-__ldg(ltemp) * L2E);
        int w = tid >> 5, lane = tid & 31;
        float ss = 0.f;
        #pragma unroll
        for (int c = lane; c < 128; c += 32) {
            float x = s_h1[w * 132 + c];
            ss = fmaf(x, x, ss);
        }
        #pragma unroll
        for (int d = 16; d > 0; d >>= 1) ss += __shfl_xor_sync(0xffffffffu, ss, d);
        if (lane == 0) g_m0[rb + w] = 0.5f * sqrtf(ss) * invT * L2E;
    }

    // ---- convert 8 H rows to swizzled bf16 hi/lo images (128-row tiles) ----
    if (tid < 128) {
        int rr = tid >> 4, c = tid & 15;
        float x[8];
        *(float4*)&x[0] = *(const float4*)&s_h1[rr * 132 + c * 8];
        *(float4*)&x[4] = *(const float4*)&s_h1[rr * 132 + c * 8 + 4];
        uint4 hi, lo;
        split8(x, hi, lo);
        int grow = rb + rr;
        int mb = grow >> 7, r = grow & 127;
        unsigned off = img_idx(r, c * 8);
        g_ahi[mb * 2048 + off] = hi;
        g_alo[mb * 2048 + off] = lo;
    }
}

// =====================================================================
// convert_keys: 4 chunks per thread, loads hoisted. grid CAP/64 x 256.
// =====================================================================
__global__ void __launch_bounds__(256)
convert_keys_kernel(const float* __restrict__ keys)
{
    int id  = blockIdx.x * 256 + threadIdx.x;   // 0..524287
    int row = id >> 2;                          // 0..131071
    int c0  = (id & 3) * 4;                     // 4 chunks of 8 cols
    int tile = row >> 7, r = row & 127;

    float x[32];
    #pragma unroll
    for (int u = 0; u < 4; u++) {
        int kc = (c0 + u) * 8;
        *(float4*)&x[u * 8]     = __ldg((const float4*)(keys + (size_t)row * 128 + kc));
        *(float4*)&x[u * 8 + 4] = __ldg((const float4*)(keys + (size_t)row * 128 + kc + 4));
    }
    #pragma unroll
    for (int u = 0; u < 4; u++) {
        int kc = (c0 + u) * 8;
        uint4 hi, lo;
        split8(&x[u * 8], hi, lo);
        unsigned off = img_idx(r, kc);
        g_khi[(size_t)tile * 2048 + off] = hi;
        g_klo[(size_t)tile * 2048 + off] = lo;
    }
}

// =====================================================================
// Phase B helpers: M=128 x N=128 tile, dual accumulators, fixed-shift
// epilogue interleaved. Steady-state syncs are PER-GROUP named barriers:
// group g = tid>>7 owns B rows [g*64, g*64+64) and VAL half g, both for
// prefetch (writers) and MMA/epilogue reads — no cross-group coupling.
// =====================================================================
template<bool DOEPI, bool FIRST>
__device__ __forceinline__ void region(
    float (&accC)[2][8][4], float (&accP)[2][8][4],
    int rel, int nt, int t0,
    unsigned sb, const unsigned char* smg,
    unsigned a_r0, unsigned a_cc0, unsigned b_r0, unsigned b_cc0,
    int tid, int lane, int wn, float scale2,
    const float (&m0_)[4], float (&sl_)[4], float (&sa_)[4],
    const float* __restrict__ values)
{
    const int g  = tid >> 7;        // wn-group (== wn for compute warps)
    const int lt = tid & 127;

    if (rel + 1 < nt) { asm volatile("cp.async.wait_group 1;" ::: "memory"); }
    else              { asm volatile("cp.async.wait_group 0;" ::: "memory"); }
    if (FIRST) __syncthreads();     // orders full-CTA prologue (A + tile0)
    else       barg(g);             // group's slice of tile rel complete

    const unsigned bhi_base = sb + OFF_B + (rel & 1) * 65536;
    const unsigned blo_base = bhi_base + 32768;
    const float* svp = (const float*)(smg + OFF_VAL + ((rel - 1) & 3) * 512) + wn * 64;

    #pragma unroll
    for (int mt = 0; mt < 2; mt++)
        #pragma unroll
        for (int j = 0; j < 8; j++)
            #pragma unroll
            for (int q = 0; q < 4; q++) accC[mt][j][q] = 0.f;

    #pragma unroll
    for (int kc = 0; kc < 8; kc++) {
        unsigned ahi[2][4], alo[2][4], bhi[4][4], blo[4][4];
        #pragma unroll
        for (int mt = 0; mt < 2; mt++) {
            unsigned off = sw_off(a_r0 + mt * 16, (unsigned)kc * 2 + a_cc0);
            ldsm4(ahi[mt], sb + OFF_AHI + off);
            ldsm4(alo[mt], sb + OFF_ALO + off);
        }
        #pragma unroll
        for (int p = 0; p < 4; p++) {
            unsigned off = sw_off(b_r0 + p * 16, (unsigned)kc * 2 + b_cc0);
            ldsm4(bhi[p], bhi_base + off);
            ldsm4(blo[p], blo_base + off);
        }
        #pragma unroll
        for (int mt = 0; mt < 2; mt++)
            #pragma unroll
            for (int j = 0; j < 8; j++) {
                const int p = j >> 1, q = (j & 1) * 2;
                mma_bf16(accC[mt][j], ahi[mt], &bhi[p][q]);
                mma_bf16(accC[mt][j], ahi[mt], &blo[p][q]);
                mma_bf16(accC[mt][j], alo[mt], &bhi[p][q]);
            }
        if (DOEPI) {   // previous tile's epilogue piece: 8 ex2 per kc
            const int slot = kc >> 1, mte = slot >> 1, h = slot & 1;
            const int jb = (kc & 1) * 4;
            #pragma unroll
            for (int jj2 = 0; jj2 < 4; jj2++) {
                const int jx = jb + jj2;
                float2 v2 = *(const float2*)(svp + jx * 8 + 2 * (lane & 3));
                float p0 = ex2(fmaf(accP[mte][jx][h * 2],     scale2, -m0_[slot]));
                float p1 = ex2(fmaf(accP[mte][jx][h * 2 + 1], scale2, -m0_[slot]));
                sl_[slot] += p0 + p1;
                sa_[slot] = fmaf(p0, v2.x, fmaf(p1, v2.y, sa_[slot]));
            }
        }
    }

    barg(g);   // group's warps done reading its slice of B stage (rel&1)
    if (rel + 2 < nt) {
        int gt = t0 + rel + 2;
        // regionalized prefetch: group g copies B rows [g*64, g*64+64)
        const uint4* kh = g_khi + (size_t)gt * 2048 + g * 1024;
        const uint4* kl = g_klo + (size_t)gt * 2048 + g * 1024;
        unsigned bbase = sb + OFF_B + (rel & 1) * 65536 + g * 16384;
        #pragma unroll
        for (int it = 0; it < 8; it++) {
            int q = it * 128 + lt;
            cp_async16(bbase + q * 16, kh + q);
            cp_async16(bbase + 16384 + 16384 + q * 16, kl + q);   // lo at +32768 from hi base
        }
        if (lt < 16)
            cp_async16(sb + OFF_VAL + ((rel + 2) & 3) * 512 + g * 256 + lt * 16,
                       values + (size_t)gt * 128 + g * 64 + lt * 4);
        cp_commit();
    } else {
        cp_commit();   // keep per-thread group counts uniform across iterations
    }
}

__device__ __forceinline__ void epi_final(
    const float (&acc)[2][8][4], int erel,
    const unsigned char* smg, int lane, int wn, float scale2,
    const float (&m0_)[4], float (&sl_)[4], float (&sa_)[4])
{
    const float* svp = (const float*)(smg + OFF_VAL + (erel & 3) * 512) + wn * 64;
    #pragma unroll
    for (int kc = 0; kc < 8; kc++) {
        const int slot = kc >> 1, mte = slot >> 1, h = slot & 1;
        const int jb = (kc & 1) * 4;
        #pragma unroll
        for (int jj2 = 0; jj2 < 4; jj2++) {
            const int jx = jb + jj2;
            float2 v2 = *(const float2*)(svp + jx * 8 + 2 * (lane & 3));
            float p0 = ex2(fmaf(acc[mte][jx][h * 2],     scale2, -m0_[slot]));
            float p1 = ex2(fmaf(acc[mte][jx][h * 2 + 1], scale2, -m0_[slot]));
            sl_[slot] += p0 + p1;
            sa_[slot] = fmaf(p0, v2.x, fmaf(p1, v2.y, sa_[slot]));
        }
    }
}

// =====================================================================
// Phase B: HMMA flash-decode, M=128 x N=128, 1 CTA/SM, dual accumulator
// buffers, fixed-shift softmax pipelined into the MMA stream, per-group
// named barriers in steady state. The LAST CTA to finish also performs
// the final combine (plain sums) and writes the output.
// Grid (8, 18), 256 threads.
// =====================================================================
__global__ void __launch_bounds__(256, 1)
phaseB_mma(const float* __restrict__ values, const float* __restrict__ log_temp,
           float* __restrict__ out)
{
    extern __shared__ __align__(16) unsigned char smg[];
    const unsigned sb = smem_u32(smg);

    const int tid  = threadIdx.x;
    const int wid  = tid >> 5;
    const int lane = tid & 31;
    const int wm   = wid & 3;
    const int wn   = wid >> 2;
    const int mblock = blockIdx.x;
    const int split  = blockIdx.y;

    const int t0 = (split * NKT) / NSPLIT;
    const int t1 = ((split + 1) * NKT) / NSPLIT;
    const int nt = t1 - t0;

    const float L2E = 1.4426950408889634f;
    const float scale2 = ex2(-__ldg(log_temp) * L2E) * L2E;

    // per-row fixed shift: slot = mt*2 + h
    float m0_[4];
    #pragma unroll
    for (int slot = 0; slot < 4; slot++) {
        int mt = slot >> 1, h = slot & 1;
        m0_[slot] = g_m0[mblock * 128 + wm * 32 + mt * 16 + h * 8 + (lane >> 2)];
    }

    // ---- prologue (full-CTA): A images + tile t0 (grp0), tile t0+1 (grp1) ----
    {
        const uint4* ah = g_ahi + mblock * 2048;
        const uint4* al = g_alo + mblock * 2048;
        #pragma unroll
        for (int it = 0; it < 8; it++) {
            int q = it * 256 + tid;
            cp_async16(sb + OFF_AHI + q * 16, ah + q);
            cp_async16(sb + OFF_ALO + q * 16, al + q);
        }
        const uint4* kh = g_khi + (size_t)t0 * 2048;
        const uint4* kl = g_klo + (size_t)t0 * 2048;
        #pragma unroll
        for (int it = 0; it < 8; it++) {
            int q = it * 256 + tid;
            cp_async16(sb + OFF_B + q * 16, kh + q);
            cp_async16(sb + OFF_B + 32768 + q * 16, kl + q);
        }
        if (tid < 32)
            cp_async16(sb + OFF_VAL + tid * 16, values + (size_t)t0 * 128 + tid * 4);
        cp_commit();
        const uint4* kh1 = g_khi + (size_t)(t0 + 1) * 2048;
        const uint4* kl1 = g_klo + (size_t)(t0 + 1) * 2048;
        #pragma unroll
        for (int it = 0; it < 8; it++) {
            int q = it * 256 + tid;
            cp_async16(sb + OFF_B + 65536 + q * 16, kh1 + q);
            cp_async16(sb + OFF_B + 65536 + 32768 + q * 16, kl1 + q);
        }
        if (tid < 32)
            cp_async16(sb + OFF_VAL + 512 + tid * 16,
                       values + (size_t)(t0 + 1) * 128 + tid * 4);
        cp_commit();
    }

    // per-lane ldmatrix sub-assignments
    const unsigned rr = lane & 7;
    const unsigned s  = lane >> 3;
    const unsigned a_r0 = (unsigned)(wm * 32) + (s & 1) * 8 + rr;
    const unsigned b_r0 = (unsigned)(wn * 64) + (s >> 1) * 8 + rr;
    const unsigned a_cc0 = (s >> 1);
    const unsigned b_cc0 = (s & 1);

    float sl_[4] = {0.f, 0.f, 0.f, 0.f}, sa_[4] = {0.f, 0.f, 0.f, 0.f};
    float accA[2][8][4], accB[2][8][4];

    region<false, true>(accA, accB, 0, nt, t0, sb, smg, a_r0, a_cc0, b_r0, b_cc0,
                        tid, lane, wn, scale2, m0_, sl_, sa_, values);
    int rel = 1;
    for (; rel + 1 < nt; rel += 2) {
        region<true, false>(accB, accA, rel, nt, t0, sb, smg, a_r0, a_cc0, b_r0, b_cc0,
                            tid, lane, wn, scale2, m0_, sl_, sa_, values);
        region<true, false>(accA, accB, rel + 1, nt, t0, sb, smg, a_r0, a_cc0, b_r0, b_cc0,
                            tid, lane, wn, scale2, m0_, sl_, sa_, values);
    }
    if (rel < nt) {
        region<true, false>(accB, accA, rel, nt, t0, sb, smg, a_r0, a_cc0, b_r0, b_cc0,
                            tid, lane, wn, scale2, m0_, sl_, sa_, values);
        rel++;
    }
    if (((nt - 1) & 1) == 0)
        epi_final(accA, nt - 1, smg, lane, wn, scale2, m0_, sl_, sa_);
    else
        epi_final(accB, nt - 1, smg, lane, wn, scale2, m0_, sl_, sa_);

    // ---- merge across the 4 lanes sharing each row (plain sums) ----
    #pragma unroll
    for (int slot = 0; slot < 4; slot++) {
        float l = sl_[slot], a = sa_[slot];
        #pragma unroll
        for (int d = 1; d < 4; d <<= 1) {
            l += __shfl_xor_sync(0xffffffffu, l, d);
            a += __shfl_xor_sync(0xffffffffu, a, d);
        }
        if ((lane & 3) == 0) {
            int mt = slot >> 1, h = slot & 1;
            int row  = mblock * 128 + wm * 32 + mt * 16 + h * 8 + (lane >> 2);
            int pidx = split * 2 + wn;
            g_pl[row * PSTRIDE + pidx] = l;
            g_pa[row * PSTRIDE + pidx] = a;
        }
    }

    // ---- last CTA performs the final combine (threadFenceReduction idiom) ----
    __threadfence();
    __syncthreads();
    unsigned* doneflag = (unsigned*)(smg + OFF_VAL);   // VAL area free now
    if (tid == 0) *doneflag = (atomicAdd(&g_done, 1u) == NCTAS - 1) ? 1u : 0u;
    __syncthreads();
    if (*doneflag) {
        __threadfence();   // acquire: see all CTAs' partials
        #pragma unroll
        for (int q = 0; q < 4; q++) {
            int row = tid * 4 + q;
            const float* pl = g_pl + row * PSTRIDE;
            const float* pa = g_pa + row * PSTRIDE;
            float l = 0.f, a = 0.f;
            #pragma unroll
            for (int p = 0; p < NPART; p++) { l += pl[p]; a += pa[p]; }
            out[row] = a / l;
        }
    }
}

// =====================================================================
extern "C" void kernel_launch(void* const* d_in, const int* in_sizes, int n_in,
                              void* d_out, int out_size)
{
    const float* obs    = (const float*)d_in[0];
    const float* action = (const float*)d_in[1];
    const float* pW     = (const float*)d_in[2];
    const float* pb     = (const float*)d_in[3];
    const float* t1W    = (const float*)d_in[4];
    const float* t1b    = (const float*)d_in[5];
    const float* t2W    = (const float*)d_in[6];
    const float* t2b    = (const float*)d_in[7];
    const float* keys   = (const float*)d_in[8];
    const float* values = (const float*)d_in[9];
    const float* ltemp  = (const float*)d_in[10];
    float* out = (float*)d_out;

    cudaFuncSetAttribute(phaseB_mma, cudaFuncAttributeMaxDynamicSharedMemorySize, SMEM_REQ);

    phaseA_kernel<<<B_ROWS / 8, 256>>>(obs, action, pW, pb, t1W, t1b, t2W, t2b, ltemp);
    convert_keys_kernel<<<CAP / 64, 256>>>(keys);
    phaseB_mma<<<dim3(MBLOCKS, NSPLIT), 256, SMEM_REQ>>>(values, ltemp, out);
}

// round 16
// speedup vs baseline: 1.1571x; 1.1571x over previous
#include <cuda_runtime.h>
#include <cuda_bf16.h>
#include <math.h>

// ---------------- Problem constants ----------------
#define B_ROWS   1024
#define OBS_DIM  512
#define ACT_DIM  64
#define KD       128
#define CAP      131072

// ---------------- Phase B config ----------------
#define MBLOCKS  8                      // 128 rows each
#define KTILE    128                    // keys per tile
#define NKT      (CAP / KTILE)          // 1024 tiles
#define NSPLIT   18                     // 8*18 = 144 CTAs = 1 wave
#define NPART    (NSPLIT * 2)           // 36 partials per row
#define PSTRIDE  40

// smem offsets (bytes, from dynamic smem base)
#define OFF_AHI  0                      // 32KB (128x128 bf16)
#define OFF_ALO  32768
#define OFF_B    65536                  // + stage*65536; hi 32KB, lo at +32768
#define OFF_VAL  196608                 // 4 slots * 512B
#define SMEM_REQ 198656

// ---------------- Device scratch (no cudaMalloc allowed) ----------------
__device__ uint4 g_khi[NKT * 2048];         // 32 MB swizzled bf16-hi key images (128-row tiles)
__device__ uint4 g_klo[NKT * 2048];         // 32 MB swizzled bf16-lo key images
__device__ uint4 g_ahi[MBLOCKS * 2048];     // swizzled bf16-hi h images (128-row tiles)
__device__ uint4 g_alo[MBLOCKS * 2048];
__device__ float g_m0 [B_ROWS];             // per-row fixed softmax shift (log2 units)
__device__ float g_pl [B_ROWS * PSTRIDE];
__device__ float g_pa [B_ROWS * PSTRIDE];

// ---------------- Helpers ----------------
__device__ __forceinline__ float ex2(float x) {
    float r; asm("ex2.approx.ftz.f32 %0, %1;" : "=f"(r) : "f"(x)); return r;
}
__device__ __forceinline__ unsigned smem_u32(const void* p) {
    return (unsigned)__cvta_generic_to_shared((void*)p);
}
__device__ __forceinline__ void cp_async16(unsigned dst, const void* src) {
    asm volatile("cp.async.cg.shared.global [%0], [%1], 16;" :: "r"(dst), "l"(src) : "memory");
}
__device__ __forceinline__ void cp_commit() {
    asm volatile("cp.async.commit_group;" ::: "memory");
}
// named barrier: 128 threads of one wn-group
__device__ __forceinline__ void barg(int g) {
    asm volatile("bar.sync %0, 128;" :: "r"(g + 1) : "memory");
}

__device__ __forceinline__ void ldsm4(unsigned* r, unsigned addr) {
    asm volatile("ldmatrix.sync.aligned.m8n8.x4.shared.b16 {%0,%1,%2,%3}, [%4];"
                 : "=r"(r[0]), "=r"(r[1]), "=r"(r[2]), "=r"(r[3]) : "r"(addr));
}
__device__ __forceinline__ void mma_bf16(float* c, const unsigned* a, const unsigned* b) {
    asm volatile("mma.sync.aligned.m16n8k16.row.col.f32.bf16.bf16.f32 "
                 "{%0,%1,%2,%3}, {%4,%5,%6,%7}, {%8,%9}, {%0,%1,%2,%3};"
                 : "+f"(c[0]), "+f"(c[1]), "+f"(c[2]), "+f"(c[3])
                 : "r"(a[0]), "r"(a[1]), "r"(a[2]), "r"(a[3]), "r"(b[0]), "r"(b[1]));
}

// Swizzled tile-image uint4 index: row r, chunk cc = k>>3; chunk stored at cc ^ (r&7).
__device__ __forceinline__ unsigned img_idx(int r, int k) {
    unsigned cc = (unsigned)(k >> 3);
    return ((unsigned)r << 4) + (cc ^ ((unsigned)r & 7u));
}
__device__ __forceinline__ unsigned sw_off(unsigned r, unsigned cc) {
    return (r << 8) + ((cc ^ (r & 7u)) << 4);
}

__device__ __forceinline__ void split8(const float* x, uint4& hi, uint4& lo) {
    unsigned h[4], l[4];
    #pragma unroll
    for (int p = 0; p < 4; p++) {
        float a = x[2 * p], b = x[2 * p + 1];
        __nv_bfloat162 hh = __floats2bfloat162_rn(a, b);
        float ar = a - __bfloat162float(__low2bfloat16(hh));
        float br = b - __bfloat162float(__high2bfloat16(hh));
        __nv_bfloat162 ll = __floats2bfloat162_rn(ar, br);
        h[p] = *reinterpret_cast<unsigned*>(&hh);
        l[p] = *reinterpret_cast<unsigned*>(&ll);
    }
    hi = make_uint4(h[0], h[1], h[2], h[3]);
    lo = make_uint4(l[0], l[1], l[2], l[3]);
}

// Stage one 128x32 fp32 weight chunk into s_w (pad-33 rows), coalesced.
__device__ __forceinline__ void stage_w(float* s_w, const float* __restrict__ W,
                                        int KIN, int k0, int tid)
{
    #pragma unroll
    for (int u = 0; u < 4; u++) {
        int idx = u * 256 + tid;
        int jjr = idx >> 3;
        int c4  = idx & 7;
        float4 w = __ldg((const float4*)(W + jjr * KIN + k0) + c4);
        float* d = s_w + jjr * 33 + c4 * 4;
        d[0] = w.x; d[1] = w.y; d[2] = w.z; d[3] = w.w;
    }
}

// =====================================================================
// Phase A: fused MLP with smem-staged weights. 4 rows/block, grid 256
// (2 CTAs/SM overlap the staging barriers). Writes swizzled bf16 hi/lo
// H images (128-row tiles) + per-row M0.
// =====================================================================
__global__ void __launch_bounds__(256)
phaseA_kernel(const float* __restrict__ obs,   const float* __restrict__ action,
              const float* __restrict__ pW,    const float* __restrict__ pb,
              const float* __restrict__ t1W,   const float* __restrict__ t1b,
              const float* __restrict__ t2W,   const float* __restrict__ t2b,
              const float* __restrict__ ltemp)
{
    __shared__ float s_obs[4 * 516];
    __shared__ float s_in [4 * 196];
    __shared__ float s_h1 [4 * 132];
    __shared__ float s_w  [128 * 33];
    __shared__ float s_rn [4];

    const int tid = threadIdx.x;
    const int rb  = blockIdx.x * 4;

    #pragma unroll
    for (int j = 0; j < 2; j++) {          // 4 rows * 128 float4 = 512
        int g  = j * 256 + tid;
        int r  = g >> 7, k4 = g & 127;
        float4 v = ((const float4*)obs)[(rb + r) * 128 + k4];
        *(float4*)&s_obs[r * 516 + k4 * 4] = v;
    }
    {                                       // action: 4 * 64 = 256
        int r = tid >> 6, a = tid & 63;
        s_in[r * 196 + 128 + a] = action[(rb + r) * 64 + a];
    }

    const int jj = tid & 127;
    const int rg = tid >> 7;                // 2 rows each

    // ---- predictor: 512 -> 128 ----
    float acc[2] = {0.f, 0.f};
    for (int c = 0; c < 16; c++) {
        __syncthreads();
        stage_w(s_w, pW, 512, c * 32, tid);
        __syncthreads();
        #pragma unroll
        for (int kk = 0; kk < 32; kk += 4) {
            float w0 = s_w[jj * 33 + kk], w1 = s_w[jj * 33 + kk + 1];
            float w2 = s_w[jj * 33 + kk + 2], w3 = s_w[jj * 33 + kk + 3];
            #pragma unroll
            for (int i = 0; i < 2; i++) {
                float4 o = *(const float4*)&s_obs[(rg * 2 + i) * 516 + c * 32 + kk];
                acc[i] = fmaf(w0, o.x, acc[i]);
                acc[i] = fmaf(w1, o.y, acc[i]);
                acc[i] = fmaf(w2, o.z, acc[i]);
                acc[i] = fmaf(w3, o.w, acc[i]);
            }
        }
    }
    float bias0 = pb[jj];
    float raw[2];
    #pragma unroll
    for (int i = 0; i < 2; i++) {
        raw[i] = acc[i] + bias0;
        s_in[(rg * 2 + i) * 196 + jj] = raw[i];
    }
    __syncthreads();

    // ---- L2 norms (warps 0..3 handle rows 0..3) ----
    {
        int w = tid >> 5, lane = tid & 31;
        if (w < 4) {
            float ss = 0.f;
            #pragma unroll
            for (int c = lane; c < 128; c += 32) {
                float x = s_in[w * 196 + c];
                ss = fmaf(x, x, ss);
            }
            #pragma unroll
            for (int d = 16; d > 0; d >>= 1) ss += __shfl_xor_sync(0xffffffffu, ss, d);
            if (lane == 0) s_rn[w] = 1.0f / fmaxf(sqrtf(ss), 1e-12f);
        }
    }
    __syncthreads();
    #pragma unroll
    for (int i = 0; i < 2; i++)
        s_in[(rg * 2 + i) * 196 + jj] = raw[i] * s_rn[rg * 2 + i];

    // ---- layer 1: 192 -> 128, relu ----
    float acc1[2] = {0.f, 0.f};
    for (int c = 0; c < 6; c++) {
        __syncthreads();
        stage_w(s_w, t1W, 192, c * 32, tid);
        __syncthreads();
        #pragma unroll
        for (int kk = 0; kk < 32; kk += 4) {
            float w0 = s_w[jj * 33 + kk], w1 = s_w[jj * 33 + kk + 1];
            float w2 = s_w[jj * 33 + kk + 2], w3 = s_w[jj * 33 + kk + 3];
            #pragma unroll
            for (int i = 0; i < 2; i++) {
                float4 o = *(const float4*)&s_in[(rg * 2 + i) * 196 + c * 32 + kk];
                acc1[i] = fmaf(w0, o.x, acc1[i]);
                acc1[i] = fmaf(w1, o.y, acc1[i]);
                acc1[i] = fmaf(w2, o.z, acc1[i]);
                acc1[i] = fmaf(w3, o.w, acc1[i]);
            }
        }
    }
    float bias1 = t1b[jj];
    __syncthreads();
    #pragma unroll
    for (int i = 0; i < 2; i++)
        s_h1[(rg * 2 + i) * 132 + jj] = fmaxf(acc1[i] + bias1, 0.0f);

    // ---- layer 2: 128 -> 128 ----
    float acc2[2] = {0.f, 0.f};
    for (int c = 0; c < 4; c++) {
        __syncthreads();
        stage_w(s_w, t2W, 128, c * 32, tid);
        __syncthreads();
        #pragma unroll
        for (int kk = 0; kk < 32; kk += 4) {
            float w0 = s_w[jj * 33 + kk], w1 = s_w[jj * 33 + kk + 1];
            float w2 = s_w[jj * 33 + kk + 2], w3 = s_w[jj * 33 + kk + 3];
            #pragma unroll
            for (int i = 0; i < 2; i++) {
                float4 o = *(const float4*)&s_h1[(rg * 2 + i) * 132 + c * 32 + kk];
                acc2[i] = fmaf(w0, o.x, acc2[i]);
                acc2[i] = fmaf(w1, o.y, acc2[i]);
                acc2[i] = fmaf(w2, o.z, acc2[i]);
                acc2[i] = fmaf(w3, o.w, acc2[i]);
            }
        }
    }
    float bias2 = t2b[jj];
    __syncthreads();
    #pragma unroll
    for (int i = 0; i < 2; i++)
        s_h1[(rg * 2 + i) * 132 + jj] = acc2[i] + bias2;   // H rows
    __syncthreads();

    // ---- per-row softmax shift M0 = 0.5*|H|*(1/T)*log2e ----
    {
        const float L2E = 1.4426950408889634f;
        float invT = ex2(-__ldg(ltemp) * L2E);
        int w = tid >> 5, lane = tid & 31;
        if (w < 4) {
            float ss = 0.f;
            #pragma unroll
            for (int c = lane; c < 128; c += 32) {
                float x = s_h1[w * 132 + c];
                ss = fmaf(x, x, ss);
            }
            #pragma unroll
            for (int d = 16; d > 0; d >>= 1) ss += __shfl_xor_sync(0xffffffffu, ss, d);
            if (lane == 0) g_m0[rb + w] = 0.5f * sqrtf(ss) * invT * L2E;
        }
    }

    // ---- convert 4 H rows to swizzled bf16 hi/lo images (128-row tiles) ----
    if (tid < 64) {
        int rr = tid >> 4, c = tid & 15;
        float x[8];
        *(float4*)&x[0] = *(const float4*)&s_h1[rr * 132 + c * 8];
        *(float4*)&x[4] = *(const float4*)&s_h1[rr * 132 + c * 8 + 4];
        uint4 hi, lo;
        split8(x, hi, lo);
        int grow = rb + rr;
        int mb = grow >> 7, r = grow & 127;
        unsigned off = img_idx(r, c * 8);
        g_ahi[mb * 2048 + off] = hi;
        g_alo[mb * 2048 + off] = lo;
    }
}

// =====================================================================
// convert_keys: 4 chunks per thread, loads hoisted. grid CAP/64 x 256.
// =====================================================================
__global__ void __launch_bounds__(256)
convert_keys_kernel(const float* __restrict__ keys)
{
    int id  = blockIdx.x * 256 + threadIdx.x;   // 0..524287
    int row = id >> 2;                          // 0..131071
    int c0  = (id & 3) * 4;                     // 4 chunks of 8 cols
    int tile = row >> 7, r = row & 127;

    float x[32];
    #pragma unroll
    for (int u = 0; u < 4; u++) {
        int kc = (c0 + u) * 8;
        *(float4*)&x[u * 8]     = __ldg((const float4*)(keys + (size_t)row * 128 + kc));
        *(float4*)&x[u * 8 + 4] = __ldg((const float4*)(keys + (size_t)row * 128 + kc + 4));
    }
    #pragma unroll
    for (int u = 0; u < 4; u++) {
        int kc = (c0 + u) * 8;
        uint4 hi, lo;
        split8(&x[u * 8], hi, lo);
        unsigned off = img_idx(r, kc);
        g_khi[(size_t)tile * 2048 + off] = hi;
        g_klo[(size_t)tile * 2048 + off] = lo;
    }
}

// =====================================================================
// Phase B helpers: M=128 x N=128 tile, dual accumulators, fixed-shift
// epilogue interleaved. Steady-state syncs are PER-GROUP named barriers:
// group g = tid>>7 owns B rows [g*64, g*64+64) and VAL half g, both for
// prefetch (writers) and MMA/epilogue reads — no cross-group coupling.
// =====================================================================
template<bool DOEPI, bool FIRST>
__device__ __forceinline__ void region(
    float (&accC)[2][8][4], float (&accP)[2][8][4],
    int rel, int nt, int t0,
    unsigned sb, const unsigned char* smg,
    unsigned a_r0, unsigned a_cc0, unsigned b_r0, unsigned b_cc0,
    int tid, int lane, int wn, float scale2,
    const float (&m0_)[4], float (&sl_)[4], float (&sa_)[4],
    const float* __restrict__ values)
{
    const int g  = tid >> 7;        // wn-group (== wn for compute warps)
    const int lt = tid & 127;

    if (rel + 1 < nt) { asm volatile("cp.async.wait_group 1;" ::: "memory"); }
    else              { asm volatile("cp.async.wait_group 0;" ::: "memory"); }
    if (FIRST) __syncthreads();     // orders full-CTA prologue (A + tile0)
    else       barg(g);             // group's slice of tile rel complete

    const unsigned bhi_base = sb + OFF_B + (rel & 1) * 65536;
    const unsigned blo_base = bhi_base + 32768;
    const float* svp = (const float*)(smg + OFF_VAL + ((rel - 1) & 3) * 512) + wn * 64;

    #pragma unroll
    for (int mt = 0; mt < 2; mt++)
        #pragma unroll
        for (int j = 0; j < 8; j++)
            #pragma unroll
            for (int q = 0; q < 4; q++) accC[mt][j][q] = 0.f;

    #pragma unroll
    for (int kc = 0; kc < 8; kc++) {
        unsigned ahi[2][4], alo[2][4], bhi[4][4], blo[4][4];
        #pragma unroll
        for (int mt = 0; mt < 2; mt++) {
            unsigned off = sw_off(a_r0 + mt * 16, (unsigned)kc * 2 + a_cc0);
            ldsm4(ahi[mt], sb + OFF_AHI + off);
            ldsm4(alo[mt], sb + OFF_ALO + off);
        }
        #pragma unroll
        for (int p = 0; p < 4; p++) {
            unsigned off = sw_off(b_r0 + p * 16, (unsigned)kc * 2 + b_cc0);
            ldsm4(bhi[p], bhi_base + off);
            ldsm4(blo[p], blo_base + off);
        }
        #pragma unroll
        for (int mt = 0; mt < 2; mt++)
            #pragma unroll
            for (int j = 0; j < 8; j++) {
                const int p = j >> 1, q = (j & 1) * 2;
                mma_bf16(accC[mt][j], ahi[mt], &bhi[p][q]);
                mma_bf16(accC[mt][j], ahi[mt], &blo[p][q]);
                mma_bf16(accC[mt][j], alo[mt], &bhi[p][q]);
            }
        if (DOEPI) {   // previous tile's epilogue piece: 8 ex2 per kc
            const int slot = kc >> 1, mte = slot >> 1, h = slot & 1;
            const int jb = (kc & 1) * 4;
            #pragma unroll
            for (int jj2 = 0; jj2 < 4; jj2++) {
                const int jx = jb + jj2;
                float2 v2 = *(const float2*)(svp + jx * 8 + 2 * (lane & 3));
                float p0 = ex2(fmaf(accP[mte][jx][h * 2],     scale2, -m0_[slot]));
                float p1 = ex2(fmaf(accP[mte][jx][h * 2 + 1], scale2, -m0_[slot]));
                sl_[slot] += p0 + p1;
                sa_[slot] = fmaf(p0, v2.x, fmaf(p1, v2.y, sa_[slot]));
            }
        }
    }

    barg(g);   // group's warps done reading its slice of B stage (rel&1)
    if (rel + 2 < nt) {
        int gt = t0 + rel + 2;
        // regionalized prefetch: group g copies B rows [g*64, g*64+64)
        const uint4* kh = g_khi + (size_t)gt * 2048 + g * 1024;
        const uint4* kl = g_klo + (size_t)gt * 2048 + g * 1024;
        unsigned bbase = sb + OFF_B + (rel & 1) * 65536 + g * 16384;
        #pragma unroll
        for (int it = 0; it < 8; it++) {
            int q = it * 128 + lt;
            cp_async16(bbase + q * 16, kh + q);
            cp_async16(bbase + 16384 + 16384 + q * 16, kl + q);   // lo at +32768 from hi base
        }
        if (lt < 16)
            cp_async16(sb + OFF_VAL + ((rel + 2) & 3) * 512 + g * 256 + lt * 16,
                       values + (size_t)gt * 128 + g * 64 + lt * 4);
        cp_commit();
    } else {
        cp_commit();   // keep per-thread group counts uniform across iterations
    }
}

__device__ __forceinline__ void epi_final(
    const float (&acc)[2][8][4], int erel,
    const unsigned char* smg, int lane, int wn, float scale2,
    const float (&m0_)[4], float (&sl_)[4], float (&sa_)[4])
{
    const float* svp = (const float*)(smg + OFF_VAL + (erel & 3) * 512) + wn * 64;
    #pragma unroll
    for (int kc = 0; kc < 8; kc++) {
        const int slot = kc >> 1, mte = slot >> 1, h = slot & 1;
        const int jb = (kc & 1) * 4;
        #pragma unroll
        for (int jj2 = 0; jj2 < 4; jj2++) {
            const int jx = jb + jj2;
            float2 v2 = *(const float2*)(svp + jx * 8 + 2 * (lane & 3));
            float p0 = ex2(fmaf(acc[mte][jx][h * 2],     scale2, -m0_[slot]));
            float p1 = ex2(fmaf(acc[mte][jx][h * 2 + 1], scale2, -m0_[slot]));
            sl_[slot] += p0 + p1;
            sa_[slot] = fmaf(p0, v2.x, fmaf(p1, v2.y, sa_[slot]));
        }
    }
}

// =====================================================================
// Phase B: HMMA flash-decode, M=128 x N=128, 1 CTA/SM, dual accumulator
// buffers, fixed-shift softmax pipelined into the MMA stream, per-group
// named barriers in steady state. Grid (8, 18), 256 threads.
// =====================================================================
__global__ void __launch_bounds__(256, 1)
phaseB_mma(const float* __restrict__ values, const float* __restrict__ log_temp)
{
    extern __shared__ __align__(16) unsigned char smg[];
    const unsigned sb = smem_u32(smg);

    const int tid  = threadIdx.x;
    const int wid  = tid >> 5;
    const int lane = tid & 31;
    const int wm   = wid & 3;
    const int wn   = wid >> 2;
    const int mblock = blockIdx.x;
    const int split  = blockIdx.y;

    const int t0 = (split * NKT) / NSPLIT;
    const int t1 = ((split + 1) * NKT) / NSPLIT;
    const int nt = t1 - t0;

    const float L2E = 1.4426950408889634f;
    const float scale2 = ex2(-__ldg(log_temp) * L2E) * L2E;

    // per-row fixed shift: slot = mt*2 + h
    float m0_[4];
    #pragma unroll
    for (int slot = 0; slot < 4; slot++) {
        int mt = slot >> 1, h = slot & 1;
        m0_[slot] = g_m0[mblock * 128 + wm * 32 + mt * 16 + h * 8 + (lane >> 2)];
    }

    // ---- prologue (full-CTA): A images + tile t0 (grp0), tile t0+1 (grp1) ----
    {
        const uint4* ah = g_ahi + mblock * 2048;
        const uint4* al = g_alo + mblock * 2048;
        #pragma unroll
        for (int it = 0; it < 8; it++) {
            int q = it * 256 + tid;
            cp_async16(sb + OFF_AHI + q * 16, ah + q);
            cp_async16(sb + OFF_ALO + q * 16, al + q);
        }
        const uint4* kh = g_khi + (size_t)t0 * 2048;
        const uint4* kl = g_klo + (size_t)t0 * 2048;
        #pragma unroll
        for (int it = 0; it < 8; it++) {
            int q = it * 256 + tid;
            cp_async16(sb + OFF_B + q * 16, kh + q);
            cp_async16(sb + OFF_B + 32768 + q * 16, kl + q);
        }
        if (tid < 32)
            cp_async16(sb + OFF_VAL + tid * 16, values + (size_t)t0 * 128 + tid * 4);
        cp_commit();
        const uint4* kh1 = g_khi + (size_t)(t0 + 1) * 2048;
        const uint4* kl1 = g_klo + (size_t)(t0 + 1) * 2048;
        #pragma unroll
        for (int it = 0; it < 8; it++) {
            int q = it * 256 + tid;
            cp_async16(sb + OFF_B + 65536 + q * 16, kh1 + q);
            cp_async16(sb + OFF_B + 65536 + 32768 + q * 16, kl1 + q);
        }
        if (tid < 32)
            cp_async16(sb + OFF_VAL + 512 + tid * 16,
                       values + (size_t)(t0 + 1) * 128 + tid * 4);
        cp_commit();
    }

    // per-lane ldmatrix sub-assignments
    const unsigned rr = lane & 7;
    const unsigned s  = lane >> 3;
    const unsigned a_r0 = (unsigned)(wm * 32) + (s & 1) * 8 + rr;
    const unsigned b_r0 = (unsigned)(wn * 64) + (s >> 1) * 8 + rr;
    const unsigned a_cc0 = (s >> 1);
    const unsigned b_cc0 = (s & 1);

    float sl_[4] = {0.f, 0.f, 0.f, 0.f}, sa_[4] = {0.f, 0.f, 0.f, 0.f};
    float accA[2][8][4], accB[2][8][4];

    region<false, true>(accA, accB, 0, nt, t0, sb, smg, a_r0, a_cc0, b_r0, b_cc0,
                        tid, lane, wn, scale2, m0_, sl_, sa_, values);
    int rel = 1;
    for (; rel + 1 < nt; rel += 2) {
        region<true, false>(accB, accA, rel, nt, t0, sb, smg, a_r0, a_cc0, b_r0, b_cc0,
                            tid, lane, wn, scale2, m0_, sl_, sa_, values);
        region<true, false>(accA, accB, rel + 1, nt, t0, sb, smg, a_r0, a_cc0, b_r0, b_cc0,
                            tid, lane, wn, scale2, m0_, sl_, sa_, values);
    }
    if (rel < nt) {
        region<true, false>(accB, accA, rel, nt, t0, sb, smg, a_r0, a_cc0, b_r0, b_cc0,
                            tid, lane, wn, scale2, m0_, sl_, sa_, values);
        rel++;
    }
    if (((nt - 1) & 1) == 0)
        epi_final(accA, nt - 1, smg, lane, wn, scale2, m0_, sl_, sa_);
    else
        epi_final(accB, nt - 1, smg, lane, wn, scale2, m0_, sl_, sa_);

    // ---- merge across the 4 lanes sharing each row (plain sums) ----
    #pragma unroll
    for (int slot = 0; slot < 4; slot++) {
        float l = sl_[slot], a = sa_[slot];
        #pragma unroll
        for (int d = 1; d < 4; d <<= 1) {
            l += __shfl_xor_sync(0xffffffffu, l, d);
            a += __shfl_xor_sync(0xffffffffu, a, d);
        }
        if ((lane & 3) == 0) {
            int mt = slot >> 1, h = slot & 1;
            int row  = mblock * 128 + wm * 32 + mt * 16 + h * 8 + (lane >> 2);
            int pidx = split * 2 + wn;
            g_pl[row * PSTRIDE + pidx] = l;
            g_pa[row * PSTRIDE + pidx] = a;
        }
    }
}

// =====================================================================
// Combine: plain sums. One warp per row.
// =====================================================================
__global__ void __launch_bounds__(256)
combine_kernel(float* __restrict__ out)
{
    const int tid  = threadIdx.x;
    const int w    = tid >> 5, lane = tid & 31;
    const int row  = blockIdx.x * 8 + w;
    const int base = row * PSTRIDE;

    float l = 0.f, a = 0.f;
    if (lane < NPART) { l = g_pl[base + lane]; a = g_pa[base + lane]; }
    if (lane + 32 < NPART) { l += g_pl[base + lane + 32]; a += g_pa[base + lane + 32]; }
    #pragma unroll
    for (int d = 16; d > 0; d >>= 1) {
        l += __shfl_xor_sync(0xffffffffu, l, d);
        a += __shfl_xor_sync(0xffffffffu, a, d);
    }
    if (lane == 0) out[row] = a / l;
}

// =====================================================================
extern "C" void kernel_launch(void* const* d_in, const int* in_sizes, int n_in,
                              void* d_out, int out_size)
{
    const float* obs    = (const float*)d_in[0];
    const float* action = (const float*)d_in[1];
    const float* pW     = (const float*)d_in[2];
    const float* pb     = (const float*)d_in[3];
    const float* t1W    = (const float*)d_in[4];
    const float* t1b    = (const float*)d_in[5];
    const float* t2W    = (const float*)d_in[6];
    const float* t2b    = (const float*)d_in[7];
    const float* keys   = (const float*)d_in[8];
    const float* values = (const float*)d_in[9];
    const float* ltemp  = (const float*)d_in[10];
    float* out = (float*)d_out;

    cudaFuncSetAttribute(phaseB_mma, cudaFuncAttributeMaxDynamicSharedMemorySize, SMEM_REQ);

    phaseA_kernel<<<B_ROWS / 4, 256>>>(obs, action, pW, pb, t1W, t1b, t2W, t2b, ltemp);
    convert_keys_kernel<<<CAP / 64, 256>>>(keys);
    phaseB_mma<<<dim3(MBLOCKS, NSPLIT), 256, SMEM_REQ>>>(values, ltemp);
    combine_kernel<<<B_ROWS / 8, 256>>>(out);
}

// round 17
// speedup vs baseline: 1.1733x; 1.0140x over previous
#include <cuda_runtime.h>
#include <cuda_bf16.h>
#include <math.h>

// ---------------- Problem constants ----------------
#define B_ROWS   1024
#define OBS_DIM  512
#define ACT_DIM  64
#define KD       128
#define CAP      131072

// ---------------- Phase B config ----------------
#define MBLOCKS  8                      // 128 rows each
#define KTILE    128                    // keys per tile
#define NKT      (CAP / KTILE)          // 1024 tiles
#define NSPLIT   18                     // 8*18 = 144 CTAs = 1 wave
#define NPART    (NSPLIT * 2)           // 36 partials per row
#define PSTRIDE  40

// smem offsets (bytes, from dynamic smem base)
#define OFF_AHI  0                      // 32KB (128x128 bf16)
#define OFF_ALO  32768
#define OFF_B    65536                  // + stage*65536; hi 32KB, lo at +32768
#define OFF_VAL  196608                 // 4 slots * 512B
#define SMEM_REQ 198656

// ---------------- Device scratch (no cudaMalloc allowed) ----------------
__device__ uint4 g_khi[NKT * 2048];         // 32 MB swizzled bf16-hi key images (128-row tiles)
__device__ uint4 g_klo[NKT * 2048];         // 32 MB swizzled bf16-lo key images
__device__ uint4 g_ahi[MBLOCKS * 2048];     // swizzled bf16-hi h images (128-row tiles)
__device__ uint4 g_alo[MBLOCKS * 2048];
__device__ float g_m0 [B_ROWS];             // per-row fixed softmax shift (log2 units)
__device__ float g_pl [B_ROWS * PSTRIDE];
__device__ float g_pa [B_ROWS * PSTRIDE];

// ---------------- Helpers ----------------
__device__ __forceinline__ float ex2(float x) {
    float r; asm("ex2.approx.ftz.f32 %0, %1;" : "=f"(r) : "f"(x)); return r;
}
__device__ __forceinline__ unsigned smem_u32(const void* p) {
    return (unsigned)__cvta_generic_to_shared((void*)p);
}
__device__ __forceinline__ void cp_async16(unsigned dst, const void* src) {
    asm volatile("cp.async.cg.shared.global [%0], [%1], 16;" :: "r"(dst), "l"(src) : "memory");
}
__device__ __forceinline__ void cp_commit() {
    asm volatile("cp.async.commit_group;" ::: "memory");
}
// named barrier: 128 threads of one wn-group
__device__ __forceinline__ void barg(int g) {
    asm volatile("bar.sync %0, 128;" :: "r"(g + 1) : "memory");
}

__device__ __forceinline__ void ldsm4(unsigned* r, unsigned addr) {
    asm volatile("ldmatrix.sync.aligned.m8n8.x4.shared.b16 {%0,%1,%2,%3}, [%4];"
                 : "=r"(r[0]), "=r"(r[1]), "=r"(r[2]), "=r"(r[3]) : "r"(addr));
}
__device__ __forceinline__ void mma_bf16(float* c, const unsigned* a, const unsigned* b) {
    asm volatile("mma.sync.aligned.m16n8k16.row.col.f32.bf16.bf16.f32 "
                 "{%0,%1,%2,%3}, {%4,%5,%6,%7}, {%8,%9}, {%0,%1,%2,%3};"
                 : "+f"(c[0]), "+f"(c[1]), "+f"(c[2]), "+f"(c[3])
                 : "r"(a[0]), "r"(a[1]), "r"(a[2]), "r"(a[3]), "r"(b[0]), "r"(b[1]));
}

// Swizzled tile-image uint4 index: row r, chunk cc = k>>3; chunk stored at cc ^ (r&7).
__device__ __forceinline__ unsigned img_idx(int r, int k) {
    unsigned cc = (unsigned)(k >> 3);
    return ((unsigned)r << 4) + (cc ^ ((unsigned)r & 7u));
}
__device__ __forceinline__ unsigned sw_off(unsigned r, unsigned cc) {
    return (r << 8) + ((cc ^ (r & 7u)) << 4);
}

__device__ __forceinline__ void split8(const float* x, uint4& hi, uint4& lo) {
    unsigned h[4], l[4];
    #pragma unroll
    for (int p = 0; p < 4; p++) {
        float a = x[2 * p], b = x[2 * p + 1];
        __nv_bfloat162 hh = __floats2bfloat162_rn(a, b);
        float ar = a - __bfloat162float(__low2bfloat16(hh));
        float br = b - __bfloat162float(__high2bfloat16(hh));
        __nv_bfloat162 ll = __floats2bfloat162_rn(ar, br);
        h[p] = *reinterpret_cast<unsigned*>(&hh);
        l[p] = *reinterpret_cast<unsigned*>(&ll);
    }
    hi = make_uint4(h[0], h[1], h[2], h[3]);
    lo = make_uint4(l[0], l[1], l[2], l[3]);
}

// load one 128x32 weight chunk into per-thread registers (coalesced)
__device__ __forceinline__ void ldw_regs(float4 (&w)[4], const float* __restrict__ W,
                                         int KIN, int k0, int tid)
{
    #pragma unroll
    for (int u = 0; u < 4; u++) {
        int idx = u * 256 + tid;
        int jjr = idx >> 3;
        int c4  = idx & 7;
        w[u] = __ldg((const float4*)(W + jjr * KIN + k0) + c4);
    }
}
// store the staged registers into s_w (pad-33 rows, conflict-free reads)
__device__ __forceinline__ void stw_regs(float* s_w, const float4 (&w)[4], int tid)
{
    #pragma unroll
    for (int u = 0; u < 4; u++) {
        int idx = u * 256 + tid;
        int jjr = idx >> 3;
        int c4  = idx & 7;
        float* d = s_w + jjr * 33 + c4 * 4;
        d[0] = w[u].x; d[1] = w[u].y; d[2] = w[u].z; d[3] = w[u].w;
    }
}

// =====================================================================
// Phase A: fused MLP, register-pipelined weight staging. 4 rows/block,
// grid 256 (2 CTAs/SM). Writes swizzled bf16 hi/lo H images + M0.
// =====================================================================
__global__ void __launch_bounds__(256)
phaseA_kernel(const float* __restrict__ obs,   const float* __restrict__ action,
              const float* __restrict__ pW,    const float* __restrict__ pb,
              const float* __restrict__ t1W,   const float* __restrict__ t1b,
              const float* __restrict__ t2W,   const float* __restrict__ t2b,
              const float* __restrict__ ltemp)
{
    __shared__ float s_obs[4 * 516];
    __shared__ float s_in [4 * 196];
    __shared__ float s_h1 [4 * 132];
    __shared__ float s_w  [128 * 33];
    __shared__ float s_rn [4];

    const int tid = threadIdx.x;
    const int rb  = blockIdx.x * 4;

    float4 wreg[4];
    ldw_regs(wreg, pW, 512, 0, tid);       // prefetch chunk 0 immediately

    #pragma unroll
    for (int j = 0; j < 2; j++) {          // 4 rows * 128 float4 = 512
        int g  = j * 256 + tid;
        int r  = g >> 7, k4 = g & 127;
        float4 v = ((const float4*)obs)[(rb + r) * 128 + k4];
        *(float4*)&s_obs[r * 516 + k4 * 4] = v;
    }
    {                                       // action: 4 * 64 = 256
        int r = tid >> 6, a = tid & 63;
        s_in[r * 196 + 128 + a] = action[(rb + r) * 64 + a];
    }
    __syncthreads();                        // obs/action staged

    const int jj = tid & 127;
    const int rg = tid >> 7;                // 2 rows each

    // ---- predictor: 512 -> 128, register-pipelined ----
    float acc[2] = {0.f, 0.f};
    for (int c = 0; c < 16; c++) {
        stw_regs(s_w, wreg, tid);
        __syncthreads();
        if (c + 1 < 16) ldw_regs(wreg, pW, 512, (c + 1) * 32, tid);
        #pragma unroll
        for (int kk = 0; kk < 32; kk += 4) {
            float w0 = s_w[jj * 33 + kk], w1 = s_w[jj * 33 + kk + 1];
            float w2 = s_w[jj * 33 + kk + 2], w3 = s_w[jj * 33 + kk + 3];
            #pragma unroll
            for (int i = 0; i < 2; i++) {
                float4 o = *(const float4*)&s_obs[(rg * 2 + i) * 516 + c * 32 + kk];
                acc[i] = fmaf(w0, o.x, acc[i]);
                acc[i] = fmaf(w1, o.y, acc[i]);
                acc[i] = fmaf(w2, o.z, acc[i]);
                acc[i] = fmaf(w3, o.w, acc[i]);
            }
        }
        __syncthreads();                    // all reads of s_w done
    }
    ldw_regs(wreg, t1W, 192, 0, tid);       // prefetch layer-1 chunk 0
    float bias0 = pb[jj];
    float raw[2];
    #pragma unroll
    for (int i = 0; i < 2; i++) {
        raw[i] = acc[i] + bias0;
        s_in[(rg * 2 + i) * 196 + jj] = raw[i];
    }
    __syncthreads();

    // ---- L2 norms (warps 0..3 handle rows 0..3) ----
    {
        int w = tid >> 5, lane = tid & 31;
        if (w < 4) {
            float ss = 0.f;
            #pragma unroll
            for (int c = lane; c < 128; c += 32) {
                float x = s_in[w * 196 + c];
                ss = fmaf(x, x, ss);
            }
            #pragma unroll
            for (int d = 16; d > 0; d >>= 1) ss += __shfl_xor_sync(0xffffffffu, ss, d);
            if (lane == 0) s_rn[w] = 1.0f / fmaxf(sqrtf(ss), 1e-12f);
        }
    }
    __syncthreads();
    #pragma unroll
    for (int i = 0; i < 2; i++)
        s_in[(rg * 2 + i) * 196 + jj] = raw[i] * s_rn[rg * 2 + i];
    __syncthreads();                        // normalized s_in visible

    // ---- layer 1: 192 -> 128, relu, register-pipelined ----
    float acc1[2] = {0.f, 0.f};
    for (int c = 0; c < 6; c++) {
        stw_regs(s_w, wreg, tid);
        __syncthreads();
        if (c + 1 < 6) ldw_regs(wreg, t1W, 192, (c + 1) * 32, tid);
        #pragma unroll
        for (int kk = 0; kk < 32; kk += 4) {
            float w0 = s_w[jj * 33 + kk], w1 = s_w[jj * 33 + kk + 1];
            float w2 = s_w[jj * 33 + kk + 2], w3 = s_w[jj * 33 + kk + 3];
            #pragma unroll
            for (int i = 0; i < 2; i++) {
                float4 o = *(const float4*)&s_in[(rg * 2 + i) * 196 + c * 32 + kk];
                acc1[i] = fmaf(w0, o.x, acc1[i]);
                acc1[i] = fmaf(w1, o.y, acc1[i]);
                acc1[i] = fmaf(w2, o.z, acc1[i]);
                acc1[i] = fmaf(w3, o.w, acc1[i]);
            }
        }
        __syncthreads();
    }
    ldw_regs(wreg, t2W, 128, 0, tid);       // prefetch layer-2 chunk 0
    float bias1 = t1b[jj];
    #pragma unroll
    for (int i = 0; i < 2; i++)
        s_h1[(rg * 2 + i) * 132 + jj] = fmaxf(acc1[i] + bias1, 0.0f);
    __syncthreads();

    // ---- layer 2: 128 -> 128, register-pipelined ----
    float acc2[2] = {0.f, 0.f};
    for (int c = 0; c < 4; c++) {
        stw_regs(s_w, wreg, tid);
        __syncthreads();
        if (c + 1 < 4) ldw_regs(wreg, t2W, 128, (c + 1) * 32, tid);
        #pragma unroll
        for (int kk = 0; kk < 32; kk += 4) {
            float w0 = s_w[jj * 33 + kk], w1 = s_w[jj * 33 + kk + 1];
            float w2 = s_w[jj * 33 + kk + 2], w3 = s_w[jj * 33 + kk + 3];
            #pragma unroll
            for (int i = 0; i < 2; i++) {
                float4 o = *(const float4*)&s_h1[(rg * 2 + i) * 132 + c * 32 + kk];
                acc2[i] = fmaf(w0, o.x, acc2[i]);
                acc2[i] = fmaf(w1, o.y, acc2[i]);
                acc2[i] = fmaf(w2, o.z, acc2[i]);
                acc2[i] = fmaf(w3, o.w, acc2[i]);
            }
        }
        __syncthreads();
    }
    float bias2 = t2b[jj];
    #pragma unroll
    for (int i = 0; i < 2; i++)
        s_h1[(rg * 2 + i) * 132 + jj] = acc2[i] + bias2;   // H rows
    __syncthreads();

    // ---- per-row softmax shift M0 = 0.5*|H|*(1/T)*log2e ----
    {
        const float L2E = 1.4426950408889634f;
        float invT = ex2(-__ldg(ltemp) * L2E);
        int w = tid >> 5, lane = tid & 31;
        if (w < 4) {
            float ss = 0.f;
            #pragma unroll
            for (int c = lane; c < 128; c += 32) {
                float x = s_h1[w * 132 + c];
                ss = fmaf(x, x, ss);
            }
            #pragma unroll
            for (int d = 16; d > 0; d >>= 1) ss += __shfl_xor_sync(0xffffffffu, ss, d);
            if (lane == 0) g_m0[rb + w] = 0.5f * sqrtf(ss) * invT * L2E;
        }
    }

    // ---- convert 4 H rows to swizzled bf16 hi/lo images (128-row tiles) ----
    if (tid < 64) {
        int rr = tid >> 4, c = tid & 15;
        float x[8];
        *(float4*)&x[0] = *(const float4*)&s_h1[rr * 132 + c * 8];
        *(float4*)&x[4] = *(const float4*)&s_h1[rr * 132 + c * 8 + 4];
        uint4 hi, lo;
        split8(x, hi, lo);
        int grow = rb + rr;
        int mb = grow >> 7, r = grow & 127;
        unsigned off = img_idx(r, c * 8);
        g_ahi[mb * 2048 + off] = hi;
        g_alo[mb * 2048 + off] = lo;
    }
}

// =====================================================================
// convert_keys: 4 chunks per thread, loads hoisted. grid CAP/64 x 256.
// =====================================================================
__global__ void __launch_bounds__(256)
convert_keys_kernel(const float* __restrict__ keys)
{
    int id  = blockIdx.x * 256 + threadIdx.x;   // 0..524287
    int row = id >> 2;                          // 0..131071
    int c0  = (id & 3) * 4;                     // 4 chunks of 8 cols
    int tile = row >> 7, r = row & 127;

    float x[32];
    #pragma unroll
    for (int u = 0; u < 4; u++) {
        int kc = (c0 + u) * 8;
        *(float4*)&x[u * 8]     = __ldg((const float4*)(keys + (size_t)row * 128 + kc));
        *(float4*)&x[u * 8 + 4] = __ldg((const float4*)(keys + (size_t)row * 128 + kc + 4));
    }
    #pragma unroll
    for (int u = 0; u < 4; u++) {
        int kc = (c0 + u) * 8;
        uint4 hi, lo;
        split8(&x[u * 8], hi, lo);
        unsigned off = img_idx(r, kc);
        g_khi[(size_t)tile * 2048 + off] = hi;
        g_klo[(size_t)tile * 2048 + off] = lo;
    }
}

// =====================================================================
// Phase B helpers: M=128 x N=128 tile, dual accumulators, fixed-shift
// epilogue interleaved. Steady-state syncs are PER-GROUP named barriers:
// group g = tid>>7 owns B rows [g*64, g*64+64) and VAL half g, both for
// prefetch (writers) and MMA/epilogue reads — no cross-group coupling.
// =====================================================================
template<bool DOEPI, bool FIRST>
__device__ __forceinline__ void region(
    float (&accC)[2][8][4], float (&accP)[2][8][4],
    int rel, int nt, int t0,
    unsigned sb, const unsigned char* smg,
    unsigned a_r0, unsigned a_cc0, unsigned b_r0, unsigned b_cc0,
    int tid, int lane, int wn, float scale2,
    const float (&m0_)[4], float (&sl_)[4], float (&sa_)[4],
    const float* __restrict__ values)
{
    const int g  = tid >> 7;        // wn-group (== wn for compute warps)
    const int lt = tid & 127;

    if (rel + 1 < nt) { asm volatile("cp.async.wait_group 1;" ::: "memory"); }
    else              { asm volatile("cp.async.wait_group 0;" ::: "memory"); }
    if (FIRST) __syncthreads();     // orders full-CTA prologue (A + tile0)
    else       barg(g);             // group's slice of tile rel complete

    const unsigned bhi_base = sb + OFF_B + (rel & 1) * 65536;
    const unsigned blo_base = bhi_base + 32768;
    const float* svp = (const float*)(smg + OFF_VAL + ((rel - 1) & 3) * 512) + wn * 64;

    #pragma unroll
    for (int mt = 0; mt < 2; mt++)
        #pragma unroll
        for (int j = 0; j < 8; j++)
            #pragma unroll
            for (int q = 0; q < 4; q++) accC[mt][j][q] = 0.f;

    #pragma unroll
    for (int kc = 0; kc < 8; kc++) {
        unsigned ahi[2][4], alo[2][4], bhi[4][4], blo[4][4];
        #pragma unroll
        for (int mt = 0; mt < 2; mt++) {
            unsigned off = sw_off(a_r0 + mt * 16, (unsigned)kc * 2 + a_cc0);
            ldsm4(ahi[mt], sb + OFF_AHI + off);
            ldsm4(alo[mt], sb + OFF_ALO + off);
        }
        #pragma unroll
        for (int p = 0; p < 4; p++) {
            unsigned off = sw_off(b_r0 + p * 16, (unsigned)kc * 2 + b_cc0);
            ldsm4(bhi[p], bhi_base + off);
            ldsm4(blo[p], blo_base + off);
        }
        #pragma unroll
        for (int mt = 0; mt < 2; mt++)
            #pragma unroll
            for (int j = 0; j < 8; j++) {
                const int p = j >> 1, q = (j & 1) * 2;
                mma_bf16(accC[mt][j], ahi[mt], &bhi[p][q]);
                mma_bf16(accC[mt][j], ahi[mt], &blo[p][q]);
                mma_bf16(accC[mt][j], alo[mt], &bhi[p][q]);
            }
        if (DOEPI) {   // previous tile's epilogue piece: 8 ex2 per kc
            const int slot = kc >> 1, mte = slot >> 1, h = slot & 1;
            const int jb = (kc & 1) * 4;
            #pragma unroll
            for (int jj2 = 0; jj2 < 4; jj2++) {
                const int jx = jb + jj2;
                float2 v2 = *(const float2*)(svp + jx * 8 + 2 * (lane & 3));
                float p0 = ex2(fmaf(accP[mte][jx][h * 2],     scale2, -m0_[slot]));
                float p1 = ex2(fmaf(accP[mte][jx][h * 2 + 1], scale2, -m0_[slot]));
                sl_[slot] += p0 + p1;
                sa_[slot] = fmaf(p0, v2.x, fmaf(p1, v2.y, sa_[slot]));
            }
        }
    }

    barg(g);   // group's warps done reading its slice of B stage (rel&1)
    if (rel + 2 < nt) {
        int gt = t0 + rel + 2;
        // regionalized prefetch: group g copies B rows [g*64, g*64+64)
        const uint4* kh = g_khi + (size_t)gt * 2048 + g * 1024;
        const uint4* kl = g_klo + (size_t)gt * 2048 + g * 1024;
        unsigned bbase = sb + OFF_B + (rel & 1) * 65536 + g * 16384;
        #pragma unroll
        for (int it = 0; it < 8; it++) {
            int q = it * 128 + lt;
            cp_async16(bbase + q * 16, kh + q);
            cp_async16(bbase + 16384 + 16384 + q * 16, kl + q);   // lo at +32768 from hi base
        }
        if (lt < 16)
            cp_async16(sb + OFF_VAL + ((rel + 2) & 3) * 512 + g * 256 + lt * 16,
                       values + (size_t)gt * 128 + g * 64 + lt * 4);
        cp_commit();
    } else {
        cp_commit();   // keep per-thread group counts uniform across iterations
    }
}

__device__ __forceinline__ void epi_final(
    const float (&acc)[2][8][4], int erel,
    const unsigned char* smg, int lane, int wn, float scale2,
    const float (&m0_)[4], float (&sl_)[4], float (&sa_)[4])
{
    const float* svp = (const float*)(smg + OFF_VAL + (erel & 3) * 512) + wn * 64;
    #pragma unroll
    for (int kc = 0; kc < 8; kc++) {
        const int slot = kc >> 1, mte = slot >> 1, h = slot & 1;
        const int jb = (kc & 1) * 4;
        #pragma unroll
        for (int jj2 = 0; jj2 < 4; jj2++) {
            const int jx = jb + jj2;
            float2 v2 = *(const float2*)(svp + jx * 8 + 2 * (lane & 3));
            float p0 = ex2(fmaf(acc[mte][jx][h * 2],     scale2, -m0_[slot]));
            float p1 = ex2(fmaf(acc[mte][jx][h * 2 + 1], scale2, -m0_[slot]));
            sl_[slot] += p0 + p1;
            sa_[slot] = fmaf(p0, v2.x, fmaf(p1, v2.y, sa_[slot]));
        }
    }
}

// =====================================================================
// Phase B: HMMA flash-decode, M=128 x N=128, 1 CTA/SM, dual accumulator
// buffers, fixed-shift softmax pipelined into the MMA stream, per-group
// named barriers in steady state. Grid (8, 18), 256 threads.
// =====================================================================
__global__ void __launch_bounds__(256, 1)
phaseB_mma(const float* __restrict__ values, const float* __restrict__ log_temp)
{
    extern __shared__ __align__(16) unsigned char smg[];
    const unsigned sb = smem_u32(smg);

    const int tid  = threadIdx.x;
    const int wid  = tid >> 5;
    const int lane = tid & 31;
    const int wm   = wid & 3;
    const int wn   = wid >> 2;
    const int mblock = blockIdx.x;
    const int split  = blockIdx.y;

    const int t0 = (split * NKT) / NSPLIT;
    const int t1 = ((split + 1) * NKT) / NSPLIT;
    const int nt = t1 - t0;

    const float L2E = 1.4426950408889634f;
    const float scale2 = ex2(-__ldg(log_temp) * L2E) * L2E;

    // per-row fixed shift: slot = mt*2 + h
    float m0_[4];
    #pragma unroll
    for (int slot = 0; slot < 4; slot++) {
        int mt = slot >> 1, h = slot & 1;
        m0_[slot] = g_m0[mblock * 128 + wm * 32 + mt * 16 + h * 8 + (lane >> 2)];
    }

    // ---- prologue (full-CTA): A images + tile t0 (grp0), tile t0+1 (grp1) ----
    {
        const uint4* ah = g_ahi + mblock * 2048;
        const uint4* al = g_alo + mblock * 2048;
        #pragma unroll
        for (int it = 0; it < 8; it++) {
            int q = it * 256 + tid;
            cp_async16(sb + OFF_AHI + q * 16, ah + q);
            cp_async16(sb + OFF_ALO + q * 16, al + q);
        }
        const uint4* kh = g_khi + (size_t)t0 * 2048;
        const uint4* kl = g_klo + (size_t)t0 * 2048;
        #pragma unroll
        for (int it = 0; it < 8; it++) {
            int q = it * 256 + tid;
            cp_async16(sb + OFF_B + q * 16, kh + q);
            cp_async16(sb + OFF_B + 32768 + q * 16, kl + q);
        }
        if (tid < 32)
            cp_async16(sb + OFF_VAL + tid * 16, values + (size_t)t0 * 128 + tid * 4);
        cp_commit();
        const uint4* kh1 = g_khi + (size_t)(t0 + 1) * 2048;
        const uint4* kl1 = g_klo + (size_t)(t0 + 1) * 2048;
        #pragma unroll
        for (int it = 0; it < 8; it++) {
            int q = it * 256 + tid;
            cp_async16(sb + OFF_B + 65536 + q * 16, kh1 + q);
            cp_async16(sb + OFF_B + 65536 + 32768 + q * 16, kl1 + q);
        }
        if (tid < 32)
            cp_async16(sb + OFF_VAL + 512 + tid * 16,
                       values + (size_t)(t0 + 1) * 128 + tid * 4);
        cp_commit();
    }

    // per-lane ldmatrix sub-assignments
    const unsigned rr = lane & 7;
    const unsigned s  = lane >> 3;
    const unsigned a_r0 = (unsigned)(wm * 32) + (s & 1) * 8 + rr;
    const unsigned b_r0 = (unsigned)(wn * 64) + (s >> 1) * 8 + rr;
    const unsigned a_cc0 = (s >> 1);
    const unsigned b_cc0 = (s & 1);

    float sl_[4] = {0.f, 0.f, 0.f, 0.f}, sa_[4] = {0.f, 0.f, 0.f, 0.f};
    float accA[2][8][4], accB[2][8][4];

    region<false, true>(accA, accB, 0, nt, t0, sb, smg, a_r0, a_cc0, b_r0, b_cc0,
                        tid, lane, wn, scale2, m0_, sl_, sa_, values);
    int rel = 1;
    for (; rel + 1 < nt; rel += 2) {
        region<true, false>(accB, accA, rel, nt, t0, sb, smg, a_r0, a_cc0, b_r0, b_cc0,
                            tid, lane, wn, scale2, m0_, sl_, sa_, values);
        region<true, false>(accA, accB, rel + 1, nt, t0, sb, smg, a_r0, a_cc0, b_r0, b_cc0,
                            tid, lane, wn, scale2, m0_, sl_, sa_, values);
    }
    if (rel < nt) {
        region<true, false>(accB, accA, rel, nt, t0, sb, smg, a_r0, a_cc0, b_r0, b_cc0,
                            tid, lane, wn, scale2, m0_, sl_, sa_, values);
        rel++;
    }
    if (((nt - 1) & 1) == 0)
        epi_final(accA, nt - 1, smg, lane, wn, scale2, m0_, sl_, sa_);
    else
        epi_final(accB, nt - 1, smg, lane, wn, scale2, m0_, sl_, sa_);

    // ---- merge across the 4 lanes sharing each row (plain sums) ----
    #pragma unroll
    for (int slot = 0; slot < 4; slot++) {
        float l = sl_[slot], a = sa_[slot];
        #pragma unroll
        for (int d = 1; d < 4; d <<= 1) {
            l += __shfl_xor_sync(0xffffffffu, l, d);
            a += __shfl_xor_sync(0xffffffffu, a, d);
        }
        if ((lane & 3) == 0) {
            int mt = slot >> 1, h = slot & 1;
            int row  = mblock * 128 + wm * 32 + mt * 16 + h * 8 + (lane >> 2);
            int pidx = split * 2 + wn;
            g_pl[row * PSTRIDE + pidx] = l;
            g_pa[row * PSTRIDE + pidx] = a;
        }
    }
}

// =====================================================================
// Combine: plain sums. One warp per row.
// =====================================================================
__global__ void __launch_bounds__(256)
combine_kernel(float* __restrict__ out)
{
    const int tid  = threadIdx.x;
    const int w    = tid >> 5, lane = tid & 31;
    const int row  = blockIdx.x * 8 + w;
    const int base = row * PSTRIDE;

    float l = 0.f, a = 0.f;
    if (lane < NPART) { l = g_pl[base + lane]; a = g_pa[base + lane]; }
    if (lane + 32 < NPART) { l += g_pl[base + lane + 32]; a += g_pa[base + lane + 32]; }
    #pragma unroll
    for (int d = 16; d > 0; d >>= 1) {
        l += __shfl_xor_sync(0xffffffffu, l, d);
        a += __shfl_xor_sync(0xffffffffu, a, d);
    }
    if (lane == 0) out[row] = a / l;
}

// =====================================================================
extern "C" void kernel_launch(void* const* d_in, const int* in_sizes, int n_in,
                              void* d_out, int out_size)
{
    const float* obs    = (const float*)d_in[0];
    const float* action = (const float*)d_in[1];
    const float* pW     = (const float*)d_in[2];
    const float* pb     = (const float*)d_in[3];
    const float* t1W    = (const float*)d_in[4];
    const float* t1b    = (const float*)d_in[5];
    const float* t2W    = (const float*)d_in[6];
    const float* t2b    = (const float*)d_in[7];
    const float* keys   = (const float*)d_in[8];
    const float* values = (const float*)d_in[9];
    const float* ltemp  = (const float*)d_in[10];
    float* out = (float*)d_out;

    cudaFuncSetAttribute(phaseB_mma, cudaFuncAttributeMaxDynamicSharedMemorySize, SMEM_REQ);

    phaseA_kernel<<<B_ROWS / 4, 256>>>(obs, action, pW, pb, t1W, t1b, t2W, t2b, ltemp);
    convert_keys_kernel<<<CAP / 64, 256>>>(keys);
    phaseB_mma<<<dim3(MBLOCKS, NSPLIT), 256, SMEM_REQ>>>(values, ltemp);
    combine_kernel<<<B_ROWS / 8, 256>>>(out);
}